// round 16
// baseline (speedup 1.0000x reference)
#include <cuda_runtime.h>
#include <cuda_fp16.h>
#include <math.h>
#include <stdint.h>

#define NN 100000
#define EE 1600000
#define CC 128
#define CAP 96
#define OUTC 10

// ---- scratch (device globals: no allocation allowed) ----
__device__ __half g_Yh[(size_t)NN * CC];      // x @ W_rel, fp16 (25.6 MB)
__device__ float  g_R0[(size_t)NN * CC];      // ping
__device__ float  g_R1[(size_t)NN * CC];      // pong
__device__ int    g_cnt[NN];
__device__ __align__(16) uint2 g_bucket[(size_t)NN * CAP]; // {src, w-bits}

// Prepacked weights: fp16, transposed [n][k], padded to 68 words/row —
// byte-identical layout to the GEMM's smem B plane (flat cp.async copy).
#define BW 68
#define B_WORDS (128 * BW)          // 8704 words = 34816 B per matrix
__device__ __align__(16) unsigned g_Wt[6][B_WORDS];

// ---------------------------------------------------------------------------
// Edge preprocessing
// ---------------------------------------------------------------------------
__global__ void k_zero_cnt() {
    int i = blockIdx.x * blockDim.x + threadIdx.x;
    if (i < NN) g_cnt[i] = 0;
}

__global__ void k_bucket(const int* __restrict__ src, const int* __restrict__ dst,
                         const float* __restrict__ ew) {
    int e = blockIdx.x * blockDim.x + threadIdx.x;
    if (e >= EE) return;
    int d = dst[e];
    int s = atomicAdd(&g_cnt[d], 1);
    if (s < CAP)
        g_bucket[(size_t)d * CAP + s] = make_uint2((unsigned)src[e], __float_as_uint(ew[e]));
}

__device__ __forceinline__ unsigned pack_f16(float x0, float x1) {
    unsigned h;
    asm("cvt.rn.f16x2.f32 %0, %1, %2;" : "=r"(h) : "f"(x1), "f"(x0));
    return h;
}

// ---------------------------------------------------------------------------
// Weight prepack: one CTA per matrix. W[k][n] fp32 -> g_Wt[mat][n*BW + k/2]
// (fp16 pairs along k, transposed, padded).
// ---------------------------------------------------------------------------
__global__ void k_prep_w(const float* __restrict__ W0, const float* __restrict__ W1,
                         const float* __restrict__ W2, const float* __restrict__ W3,
                         const float* __restrict__ W4, const float* __restrict__ W5) {
    const float* Ws[6] = { W0, W1, W2, W3, W4, W5 };
    const float* W = Ws[blockIdx.x];
    unsigned* out = g_Wt[blockIdx.x];
    int tid = threadIdx.x;
    int n   = tid & 127;
    int kh  = tid >> 7;                 // 0..1
    #pragma unroll
    for (int i = 0; i < 16; i++) {
        int k = kh * 64 + i * 4;
        float w0 = W[(size_t)(k    ) * CC + n];
        float w1 = W[(size_t)(k + 1) * CC + n];
        float w2 = W[(size_t)(k + 2) * CC + n];
        float w3 = W[(size_t)(k + 3) * CC + n];
        ((uint2*)out)[n * 34 + (k >> 2)] =
            make_uint2(pack_f16(w0, w1), pack_f16(w2, w3));
    }
}

// ---------------------------------------------------------------------------
// Single-pass fp16 tensor-core dual GEMM (m16n8k16), N=128 per CTA.
//   grid (782, 2): by=0 -> Y = act(X)@Wrel (fp16 out)
//                  by=1 -> R = act(X)@Wroot + b (fp32 out)
//   B plane: flat cp.async copy of prepacked g_Wt (issued first, hidden
//   under A load+cvt+ReLU staging). Mainloop: LDS.32 conflict-free + HMMA.
// ---------------------------------------------------------------------------
#define AW 68
#define A_WORDS (128 * AW)          // 8704
#define GEMM_SMEM ((A_WORDS + B_WORDS) * 4)   // 69632 B

__device__ __forceinline__ void mma_f16(float4& d,
                                        const unsigned a[4], const unsigned b[2]) {
    asm volatile(
        "mma.sync.aligned.m16n8k16.row.col.f32.f16.f16.f32 "
        "{%0,%1,%2,%3}, {%4,%5,%6,%7}, {%8,%9}, {%0,%1,%2,%3};\n"
        : "+f"(d.x), "+f"(d.y), "+f"(d.z), "+f"(d.w)
        : "r"(a[0]), "r"(a[1]), "r"(a[2]), "r"(a[3]), "r"(b[0]), "r"(b[1]));
}

__global__ __launch_bounds__(256, 2)
void k_gemm_dual(const float* __restrict__ Xext,
                 int in_sel,              // 0: Xext, 1: g_R0 (ReLU), 2: g_R1 (ReLU)
                 int out_sel,             // 0: R=g_R0, 1: R=g_R1
                 int wsel_base,           // layer*2 : rel idx, +1 root idx
                 const float* __restrict__ bias)
{
    extern __shared__ unsigned sw[];
    unsigned* Ah = sw;
    unsigned* Bh = sw + A_WORDS;

    const float* X = (in_sel == 0) ? Xext : (in_sel == 1 ? g_R0 : g_R1);
    const int relu_in = (in_sel != 0);
    const int is_root = (blockIdx.y != 0);

    const int tid  = threadIdx.x;
    const int row0 = blockIdx.x * 128;

    // ---- B: flat async copy of prepacked plane (2176 uint4) ----
    {
        const uint4* Bg = (const uint4*)g_Wt[wsel_base + is_root];
        uint32_t bsm = (uint32_t)__cvta_generic_to_shared(Bh);
        #pragma unroll
        for (int i = 0; i < 9; i++) {
            int idx = tid + i * 256;
            if (idx < B_WORDS / 4)
                asm volatile("cp.async.cg.shared.global [%0], [%1], 16;\n"
                             :: "r"(bsm + idx * 16), "l"(Bg + idx));
        }
        asm volatile("cp.async.commit_group;\n");
    }

    // ---- stage A (128x128): load fp32, ReLU, pack fp16 ----
    #pragma unroll
    for (int i = 0; i < 16; i++) {
        int f4 = tid + i * 256;
        int r = f4 >> 5, c4 = f4 & 31;
        float4 v = make_float4(0.f, 0.f, 0.f, 0.f);
        if (row0 + r < NN)
            v = *(const float4*)(X + (size_t)(row0 + r) * CC + c4 * 4);
        if (relu_in) {
            v.x = fmaxf(v.x, 0.f); v.y = fmaxf(v.y, 0.f);
            v.z = fmaxf(v.z, 0.f); v.w = fmaxf(v.w, 0.f);
        }
        ((uint2*)Ah)[r * 34 + c4] =
            make_uint2(pack_f16(v.x, v.y), pack_f16(v.z, v.w));
    }
    asm volatile("cp.async.wait_group 0;\n" ::: "memory");
    __syncthreads();

    const int lane = tid & 31;
    const int w    = tid >> 5;         // 0..7
    const int wm   = w & 3;            // 0..3 : rows wm*32
    const int wn   = w >> 2;           // 0..1 : cols wn*64
    const int gr   = lane >> 2;        // 0..7
    const int tg   = lane & 3;         // 0..3

    float4 acc[2][8];
    #pragma unroll
    for (int mt = 0; mt < 2; mt++)
        #pragma unroll
        for (int nt = 0; nt < 8; nt++)
            acc[mt][nt] = make_float4(0.f, 0.f, 0.f, 0.f);

    #pragma unroll
    for (int ks = 0; ks < 8; ks++) {
        const int kw = ks * 8;
        unsigned ah[2][4], bh[8][2];
        #pragma unroll
        for (int mt = 0; mt < 2; mt++) {
            int r = wm * 32 + mt * 16 + gr;
            int i0 = r * AW + kw + tg;
            int i1 = (r + 8) * AW + kw + tg;
            ah[mt][0] = Ah[i0];     ah[mt][1] = Ah[i1];
            ah[mt][2] = Ah[i0 + 4]; ah[mt][3] = Ah[i1 + 4];
        }
        #pragma unroll
        for (int nt = 0; nt < 8; nt++) {
            int n = wn * 64 + nt * 8 + gr;
            int j0 = n * BW + kw + tg;
            bh[nt][0] = Bh[j0]; bh[nt][1] = Bh[j0 + 4];
        }
        #pragma unroll
        for (int mt = 0; mt < 2; mt++)
            #pragma unroll
            for (int nt = 0; nt < 8; nt++)
                mma_f16(acc[mt][nt], ah[mt], bh[nt]);
    }

    // ---- epilogue ----
    float* Rout = out_sel ? g_R1 : g_R0;
    #pragma unroll
    for (int mt = 0; mt < 2; mt++) {
        #pragma unroll
        for (int nt = 0; nt < 8; nt++) {
            int cg = wn * 64 + nt * 8 + tg * 2;
            int r  = row0 + wm * 32 + mt * 16 + gr;
            if (is_root) {
                float b0 = __ldg(bias + cg), b1 = __ldg(bias + cg + 1);
                if (r < NN)
                    *(float2*)(Rout + (size_t)r * CC + cg) =
                        make_float2(acc[mt][nt].x + b0, acc[mt][nt].y + b1);
                if (r + 8 < NN)
                    *(float2*)(Rout + (size_t)(r + 8) * CC + cg) =
                        make_float2(acc[mt][nt].z + b0, acc[mt][nt].w + b1);
            } else {
                if (r < NN)
                    *(__half2*)(g_Yh + (size_t)r * CC + cg) =
                        __floats2half2_rn(acc[mt][nt].x, acc[mt][nt].y);
                if (r + 8 < NN)
                    *(__half2*)(g_Yh + (size_t)(r + 8) * CC + cg) =
                        __floats2half2_rn(acc[mt][nt].z, acc[mt][nt].w);
            }
        }
    }
}

// ---------------------------------------------------------------------------
// Aggregation (R5-proven): shfl edge broadcast, fp16 gather, x2 unroll.
// ---------------------------------------------------------------------------
__global__ __launch_bounds__(256)
void k_agg(int out_sel) {
    float* R = out_sel ? g_R1 : g_R0;
    int gw   = (blockIdx.x * blockDim.x + threadIdx.x) >> 5;
    int lane = threadIdx.x & 31;
    if (gw >= NN) return;

    int deg = min(g_cnt[gw], CAP);
    float4 acc0 = *(float4*)(R + (size_t)gw * CC + lane * 4);
    float4 acc1 = make_float4(0.f, 0.f, 0.f, 0.f);
    const uint2* bk = g_bucket + (size_t)gw * CAP;

    for (int base = 0; base < deg; base += 32) {
        int m = min(32, deg - base);
        uint2 e = make_uint2(0u, 0u);
        if (lane < m) e = bk[base + lane];
        int k = 0;
        for (; k + 2 <= m; k += 2) {
            int   s0 = __shfl_sync(0xffffffffu, (int)e.x, k);
            int   s1 = __shfl_sync(0xffffffffu, (int)e.x, k + 1);
            float w0 = __int_as_float(__shfl_sync(0xffffffffu, (int)e.y, k));
            float w1 = __int_as_float(__shfl_sync(0xffffffffu, (int)e.y, k + 1));
            uint2 p0 = *(const uint2*)(g_Yh + (size_t)s0 * CC + lane * 4);
            uint2 p1 = *(const uint2*)(g_Yh + (size_t)s1 * CC + lane * 4);
            float2 a0 = __half22float2(*(const __half2*)&p0.x);
            float2 a1 = __half22float2(*(const __half2*)&p0.y);
            float2 c0 = __half22float2(*(const __half2*)&p1.x);
            float2 c1 = __half22float2(*(const __half2*)&p1.y);
            acc0.x += w0 * a0.x; acc0.y += w0 * a0.y;
            acc0.z += w0 * a1.x; acc0.w += w0 * a1.y;
            acc1.x += w1 * c0.x; acc1.y += w1 * c0.y;
            acc1.z += w1 * c1.x; acc1.w += w1 * c1.y;
        }
        if (k < m) {
            int   s  = __shfl_sync(0xffffffffu, (int)e.x, k);
            float wt = __int_as_float(__shfl_sync(0xffffffffu, (int)e.y, k));
            uint2 p  = *(const uint2*)(g_Yh + (size_t)s * CC + lane * 4);
            float2 a0 = __half22float2(*(const __half2*)&p.x);
            float2 a1 = __half22float2(*(const __half2*)&p.y);
            acc0.x += wt * a0.x; acc0.y += wt * a0.y;
            acc0.z += wt * a1.x; acc0.w += wt * a1.y;
        }
    }
    acc0.x += acc1.x; acc0.y += acc1.y; acc0.z += acc1.z; acc0.w += acc1.w;
    *(float4*)(R + (size_t)gw * CC + lane * 4) = acc0;
}

// ---------------------------------------------------------------------------
// Head: logits = relu(R0) @ W_lin + b ; log_softmax  (warp per node)
// ---------------------------------------------------------------------------
__global__ __launch_bounds__(256)
void k_head(const float* __restrict__ W, const float* __restrict__ b,
            float* __restrict__ out) {
    __shared__ float Wt[OUTC][CC];
    __shared__ float bs[OUTC];
    for (int i = threadIdx.x; i < OUTC * CC; i += 256) {
        int c = i / CC, j = i % CC;
        Wt[c][j] = W[j * OUTC + c];
    }
    if (threadIdx.x < OUTC) bs[threadIdx.x] = b[threadIdx.x];
    __syncthreads();

    int gw   = (blockIdx.x * blockDim.x + threadIdx.x) >> 5;
    int lane = threadIdx.x & 31;
    if (gw >= NN) return;

    float4 x = *(const float4*)(g_R0 + (size_t)gw * CC + lane * 4);
    x.x = fmaxf(x.x, 0.f); x.y = fmaxf(x.y, 0.f);
    x.z = fmaxf(x.z, 0.f); x.w = fmaxf(x.w, 0.f);

    float p[OUTC];
    #pragma unroll
    for (int c = 0; c < OUTC; c++) {
        float4 wv = *(const float4*)&Wt[c][lane * 4];
        float t = x.x * wv.x + x.y * wv.y + x.z * wv.z + x.w * wv.w;
        #pragma unroll
        for (int off = 16; off > 0; off >>= 1)
            t += __shfl_xor_sync(0xffffffffu, t, off);
        p[c] = t + bs[c];
    }
    float mx = p[0];
    #pragma unroll
    for (int c = 1; c < OUTC; c++) mx = fmaxf(mx, p[c]);
    float se = 0.f;
    #pragma unroll
    for (int c = 0; c < OUTC; c++) se += expf(p[c] - mx);
    float lse = mx + logf(se);
    if (lane == 0) {
        #pragma unroll
        for (int c = 0; c < OUTC; c++)
            out[(size_t)gw * OUTC + c] = p[c] - lse;
    }
}

// ---------------------------------------------------------------------------
extern "C" void kernel_launch(void* const* d_in, const int* in_sizes, int n_in,
                              void* d_out, int out_size) {
    const float* x0  = (const float*)d_in[0];
    const int*   ei  = (const int*)  d_in[1];
    const float* ew  = (const float*)d_in[2];
    const float* W1r = (const float*)d_in[3];
    const float* b1  = (const float*)d_in[4];
    const float* W1o = (const float*)d_in[5];
    const float* W2r = (const float*)d_in[6];
    const float* b2  = (const float*)d_in[7];
    const float* W2o = (const float*)d_in[8];
    const float* W3r = (const float*)d_in[9];
    const float* b3  = (const float*)d_in[10];
    const float* W3o = (const float*)d_in[11];
    const float* Wl  = (const float*)d_in[12];
    const float* bl  = (const float*)d_in[13];
    float* out = (float*)d_out;

    cudaFuncSetAttribute(k_gemm_dual, cudaFuncAttributeMaxDynamicSharedMemorySize,
                         GEMM_SMEM);

    // launch 0..2: zero, bucket, weight prepack
    k_zero_cnt<<<(NN + 255) / 256, 256>>>();
    k_bucket<<<(EE + 255) / 256, 256>>>(ei, ei + EE, ew);
    k_prep_w<<<6, 256>>>(W1r, W1o, W2r, W2o, W3r, W3o);

    dim3 ggrid((NN + 127) / 128, 2);   // 782 x 2

    // layer 1 (launches 3,4): x0 -> (Yh, R0); scatter into R0
    k_gemm_dual<<<ggrid, 256, GEMM_SMEM>>>(x0, 0, 0, 0, b1);
    k_agg<<<NN / 8, 256>>>(0);
    // layer 2 (launch 5 = ncu capture): relu(R0) -> (Yh, R1); scatter into R1
    k_gemm_dual<<<ggrid, 256, GEMM_SMEM>>>(nullptr, 1, 1, 2, b2);
    k_agg<<<NN / 8, 256>>>(1);
    // layer 3: relu(R1) -> (Yh, R0); scatter into R0
    k_gemm_dual<<<ggrid, 256, GEMM_SMEM>>>(nullptr, 2, 0, 4, b3);
    k_agg<<<NN / 8, 256>>>(0);
    // head
    k_head<<<NN / 8, 256>>>(Wl, bl, out);
}

// round 17
// speedup vs baseline: 1.0061x; 1.0061x over previous
#include <cuda_runtime.h>
#include <cuda_fp16.h>
#include <math.h>
#include <stdint.h>

#define NN 100000
#define EE 1600000
#define CC 128
#define CAP 96
#define OUTC 10

// ---- scratch (device globals: no allocation allowed) ----
__device__ __half g_Yh[(size_t)NN * CC];      // x @ W_rel, fp16 (25.6 MB)
__device__ __half g_Xh[(size_t)NN * CC];      // layer input, fp16 (25.6 MB)
__device__ float  g_R[(size_t)NN * CC];       // root+bias part, fp32 (51.2 MB)
__device__ int    g_cnt[NN];
__device__ __align__(16) uint2 g_bucket[(size_t)NN * CAP]; // {src, w-bits}

// Prepacked weights: fp16, transposed [n][k], padded to 68 words/row —
// byte-identical to the GEMM smem B plane (flat cp.async copy).
#define BW 68
#define B_WORDS (128 * BW)          // 8704 words = 34816 B per matrix
__device__ __align__(16) unsigned g_Wt[6][B_WORDS];

// ---------------------------------------------------------------------------
// Edge preprocessing
// ---------------------------------------------------------------------------
__global__ void k_zero_cnt(int base) {
    int i = base + blockIdx.x * blockDim.x + threadIdx.x;
    if (i < NN) g_cnt[i] = 0;
}

__global__ void k_bucket(const int* __restrict__ src, const int* __restrict__ dst,
                         const float* __restrict__ ew) {
    int e = blockIdx.x * blockDim.x + threadIdx.x;
    if (e >= EE) return;
    int d = dst[e];
    int s = atomicAdd(&g_cnt[d], 1);
    if (s < CAP)
        g_bucket[(size_t)d * CAP + s] = make_uint2((unsigned)src[e], __float_as_uint(ew[e]));
}

__device__ __forceinline__ unsigned pack_f16(float x0, float x1) {
    unsigned h;
    asm("cvt.rn.f16x2.f32 %0, %1, %2;" : "=r"(h) : "f"(x1), "f"(x0));
    return h;
}

// ---------------------------------------------------------------------------
// Weight prepack: one CTA per matrix. W[k][n] fp32 -> g_Wt[mat][n*BW + k/2]
// ---------------------------------------------------------------------------
__global__ void k_prep_w(const float* __restrict__ W0, const float* __restrict__ W1,
                         const float* __restrict__ W2, const float* __restrict__ W3,
                         const float* __restrict__ W4, const float* __restrict__ W5) {
    const float* Ws[6] = { W0, W1, W2, W3, W4, W5 };
    const float* W = Ws[blockIdx.x];
    unsigned* out = g_Wt[blockIdx.x];
    int tid = threadIdx.x;
    int n   = tid & 127;
    int kh  = tid >> 7;
    #pragma unroll
    for (int i = 0; i < 16; i++) {
        int k = kh * 64 + i * 4;
        float w0 = W[(size_t)(k    ) * CC + n];
        float w1 = W[(size_t)(k + 1) * CC + n];
        float w2 = W[(size_t)(k + 2) * CC + n];
        float w3 = W[(size_t)(k + 3) * CC + n];
        ((uint2*)out)[n * 34 + (k >> 2)] =
            make_uint2(pack_f16(w0, w1), pack_f16(w2, w3));
    }
}

// ---------------------------------------------------------------------------
// x0 -> fp16 (once; layer-1 GEMM input). 3.2M float4.
// ---------------------------------------------------------------------------
__global__ void k_x0h(const float4* __restrict__ x0) {
    int i = blockIdx.x * blockDim.x + threadIdx.x;
    if (i >= NN * CC / 4) return;
    float4 v = x0[i];
    ((uint2*)g_Xh)[i] = make_uint2(pack_f16(v.x, v.y), pack_f16(v.z, v.w));
}

// ---------------------------------------------------------------------------
// fp16 tensor-core dual GEMM, CTA tile 64(m) x 128(n), 8 warps x (32x32).
//   grid (1563, 2): by=0 -> Y = Xh@Wrel (fp16 out) ; by=1 -> R = Xh@Wroot + b
//   A and B planes both flat cp.async (A from g_Xh fp16, B from g_Wt).
//   Mainloop: LDS.32 conflict-free (bank = 4*gr + tg + const) + HMMA.
//   ~70 regs -> 3 CTAs/SM (24 warps).
// ---------------------------------------------------------------------------
#define AW 68
#define AM 64
#define A_WORDS (AM * AW)           // 4352
#define GEMM_SMEM ((A_WORDS + B_WORDS) * 4)   // 52224 B

__device__ __forceinline__ void mma_f16(float4& d,
                                        const unsigned a[4], const unsigned b[2]) {
    asm volatile(
        "mma.sync.aligned.m16n8k16.row.col.f32.f16.f16.f32 "
        "{%0,%1,%2,%3}, {%4,%5,%6,%7}, {%8,%9}, {%0,%1,%2,%3};\n"
        : "+f"(d.x), "+f"(d.y), "+f"(d.z), "+f"(d.w)
        : "r"(a[0]), "r"(a[1]), "r"(a[2]), "r"(a[3]), "r"(b[0]), "r"(b[1]));
}

__global__ __launch_bounds__(256, 3)
void k_gemm_dual(int wsel_base,          // layer*2 (+1 for root via blockIdx.y)
                 const float* __restrict__ bias)
{
    extern __shared__ unsigned sw[];
    unsigned* Ah = sw;
    unsigned* Bh = sw + A_WORDS;

    const int is_root = (blockIdx.y != 0);
    const int tid  = threadIdx.x;
    const int row0 = blockIdx.x * AM;

    // ---- A: flat cp.async of fp16 rows (64 x 256B, padded to 272B) ----
    {
        uint32_t asm_ = (uint32_t)__cvta_generic_to_shared(Ah);
        #pragma unroll
        for (int i = 0; i < 4; i++) {
            int idx = tid + i * 256;       // 0..1023
            int r = idx >> 4, q = idx & 15;
            uint32_t dst = asm_ + (r * AW + q * 4) * 4;
            if (row0 + r < NN) {
                const uint4* src = (const uint4*)(g_Xh + (size_t)(row0 + r) * CC) + q;
                asm volatile("cp.async.cg.shared.global [%0], [%1], 16;\n"
                             :: "r"(dst), "l"(src));
            } else {
                *(uint4*)((char*)Ah + (r * AW + q * 4) * 4) =
                    make_uint4(0u, 0u, 0u, 0u);
            }
        }
    }
    // ---- B: flat cp.async of prepacked plane (2176 uint4) ----
    {
        const uint4* Bg = (const uint4*)g_Wt[wsel_base + is_root];
        uint32_t bsm = (uint32_t)__cvta_generic_to_shared(Bh);
        #pragma unroll
        for (int i = 0; i < 9; i++) {
            int idx = tid + i * 256;
            if (idx < B_WORDS / 4)
                asm volatile("cp.async.cg.shared.global [%0], [%1], 16;\n"
                             :: "r"(bsm + idx * 16), "l"(Bg + idx));
        }
    }
    asm volatile("cp.async.commit_group;\n");
    asm volatile("cp.async.wait_group 0;\n" ::: "memory");
    __syncthreads();

    const int lane = tid & 31;
    const int w    = tid >> 5;         // 0..7
    const int wm   = w & 1;            // 0..1 : rows wm*32
    const int wn   = w >> 1;           // 0..3 : cols wn*32
    const int gr   = lane >> 2;        // 0..7
    const int tg   = lane & 3;         // 0..3

    float4 acc[2][4];
    #pragma unroll
    for (int mt = 0; mt < 2; mt++)
        #pragma unroll
        for (int nt = 0; nt < 4; nt++)
            acc[mt][nt] = make_float4(0.f, 0.f, 0.f, 0.f);

    #pragma unroll
    for (int ks = 0; ks < 8; ks++) {
        const int kw = ks * 8;
        unsigned ah[2][4], bh[4][2];
        #pragma unroll
        for (int mt = 0; mt < 2; mt++) {
            int r = wm * 32 + mt * 16 + gr;
            int i0 = r * AW + kw + tg;
            int i1 = (r + 8) * AW + kw + tg;
            ah[mt][0] = Ah[i0];     ah[mt][1] = Ah[i1];
            ah[mt][2] = Ah[i0 + 4]; ah[mt][3] = Ah[i1 + 4];
        }
        #pragma unroll
        for (int nt = 0; nt < 4; nt++) {
            int n = wn * 32 + nt * 8 + gr;
            int j0 = n * BW + kw + tg;
            bh[nt][0] = Bh[j0]; bh[nt][1] = Bh[j0 + 4];
        }
        #pragma unroll
        for (int mt = 0; mt < 2; mt++)
            #pragma unroll
            for (int nt = 0; nt < 4; nt++)
                mma_f16(acc[mt][nt], ah[mt], bh[nt]);
    }

    // ---- epilogue ----
    #pragma unroll
    for (int mt = 0; mt < 2; mt++) {
        #pragma unroll
        for (int nt = 0; nt < 4; nt++) {
            int cg = wn * 32 + nt * 8 + tg * 2;
            int r  = row0 + wm * 32 + mt * 16 + gr;
            if (is_root) {
                float b0 = __ldg(bias + cg), b1 = __ldg(bias + cg + 1);
                if (r < NN)
                    *(float2*)(g_R + (size_t)r * CC + cg) =
                        make_float2(acc[mt][nt].x + b0, acc[mt][nt].y + b1);
                if (r + 8 < NN)
                    *(float2*)(g_R + (size_t)(r + 8) * CC + cg) =
                        make_float2(acc[mt][nt].z + b0, acc[mt][nt].w + b1);
            } else {
                if (r < NN)
                    *(__half2*)(g_Yh + (size_t)r * CC + cg) =
                        __floats2half2_rn(acc[mt][nt].x, acc[mt][nt].y);
                if (r + 8 < NN)
                    *(__half2*)(g_Yh + (size_t)(r + 8) * CC + cg) =
                        __floats2half2_rn(acc[mt][nt].z, acc[mt][nt].w);
            }
        }
    }
}

// ---------------------------------------------------------------------------
// Aggregation: Xh[n] = relu( R[n] + sum_{e: dst=n} w_e * Yh[src_e] )  fp16 out
// (shfl edge broadcast, fp16 gather, x2 unroll — R5-proven core)
// ---------------------------------------------------------------------------
__global__ __launch_bounds__(256)
void k_agg() {
    int gw   = (blockIdx.x * blockDim.x + threadIdx.x) >> 5;
    int lane = threadIdx.x & 31;
    if (gw >= NN) return;

    int deg = min(g_cnt[gw], CAP);
    float4 acc0 = *(float4*)(g_R + (size_t)gw * CC + lane * 4);
    float4 acc1 = make_float4(0.f, 0.f, 0.f, 0.f);
    const uint2* bk = g_bucket + (size_t)gw * CAP;

    for (int base = 0; base < deg; base += 32) {
        int m = min(32, deg - base);
        uint2 e = make_uint2(0u, 0u);
        if (lane < m) e = bk[base + lane];
        int k = 0;
        for (; k + 2 <= m; k += 2) {
            int   s0 = __shfl_sync(0xffffffffu, (int)e.x, k);
            int   s1 = __shfl_sync(0xffffffffu, (int)e.x, k + 1);
            float w0 = __int_as_float(__shfl_sync(0xffffffffu, (int)e.y, k));
            float w1 = __int_as_float(__shfl_sync(0xffffffffu, (int)e.y, k + 1));
            uint2 p0 = *(const uint2*)(g_Yh + (size_t)s0 * CC + lane * 4);
            uint2 p1 = *(const uint2*)(g_Yh + (size_t)s1 * CC + lane * 4);
            float2 a0 = __half22float2(*(const __half2*)&p0.x);
            float2 a1 = __half22float2(*(const __half2*)&p0.y);
            float2 c0 = __half22float2(*(const __half2*)&p1.x);
            float2 c1 = __half22float2(*(const __half2*)&p1.y);
            acc0.x += w0 * a0.x; acc0.y += w0 * a0.y;
            acc0.z += w0 * a1.x; acc0.w += w0 * a1.y;
            acc1.x += w1 * c0.x; acc1.y += w1 * c0.y;
            acc1.z += w1 * c1.x; acc1.w += w1 * c1.y;
        }
        if (k < m) {
            int   s  = __shfl_sync(0xffffffffu, (int)e.x, k);
            float wt = __int_as_float(__shfl_sync(0xffffffffu, (int)e.y, k));
            uint2 p  = *(const uint2*)(g_Yh + (size_t)s * CC + lane * 4);
            float2 a0 = __half22float2(*(const __half2*)&p.x);
            float2 a1 = __half22float2(*(const __half2*)&p.y);
            acc0.x += wt * a0.x; acc0.y += wt * a0.y;
            acc0.z += wt * a1.x; acc0.w += wt * a1.y;
        }
    }
    acc0.x = fmaxf(acc0.x + acc1.x, 0.f);
    acc0.y = fmaxf(acc0.y + acc1.y, 0.f);
    acc0.z = fmaxf(acc0.z + acc1.z, 0.f);
    acc0.w = fmaxf(acc0.w + acc1.w, 0.f);
    *(uint2*)(g_Xh + (size_t)gw * CC + lane * 4) =
        make_uint2(pack_f16(acc0.x, acc0.y), pack_f16(acc0.z, acc0.w));
}

// ---------------------------------------------------------------------------
// Head: logits = Xh @ W_lin + b ; log_softmax  (Xh already relu'd, fp16)
// ---------------------------------------------------------------------------
__global__ __launch_bounds__(256)
void k_head(const float* __restrict__ W, const float* __restrict__ b,
            float* __restrict__ out) {
    __shared__ float Wt[OUTC][CC];
    __shared__ float bs[OUTC];
    for (int i = threadIdx.x; i < OUTC * CC; i += 256) {
        int c = i / CC, j = i % CC;
        Wt[c][j] = W[j * OUTC + c];
    }
    if (threadIdx.x < OUTC) bs[threadIdx.x] = b[threadIdx.x];
    __syncthreads();

    int gw   = (blockIdx.x * blockDim.x + threadIdx.x) >> 5;
    int lane = threadIdx.x & 31;
    if (gw >= NN) return;

    uint2 px = *(const uint2*)(g_Xh + (size_t)gw * CC + lane * 4);
    float2 x0 = __half22float2(*(const __half2*)&px.x);
    float2 x1 = __half22float2(*(const __half2*)&px.y);

    float p[OUTC];
    #pragma unroll
    for (int c = 0; c < OUTC; c++) {
        float4 wv = *(const float4*)&Wt[c][lane * 4];
        float t = x0.x * wv.x + x0.y * wv.y + x1.x * wv.z + x1.y * wv.w;
        #pragma unroll
        for (int off = 16; off > 0; off >>= 1)
            t += __shfl_xor_sync(0xffffffffu, t, off);
        p[c] = t + bs[c];
    }
    float mx = p[0];
    #pragma unroll
    for (int c = 1; c < OUTC; c++) mx = fmaxf(mx, p[c]);
    float se = 0.f;
    #pragma unroll
    for (int c = 0; c < OUTC; c++) se += expf(p[c] - mx);
    float lse = mx + logf(se);
    if (lane == 0) {
        #pragma unroll
        for (int c = 0; c < OUTC; c++)
            out[(size_t)gw * OUTC + c] = p[c] - lse;
    }
}

// ---------------------------------------------------------------------------
extern "C" void kernel_launch(void* const* d_in, const int* in_sizes, int n_in,
                              void* d_out, int out_size) {
    const float* x0  = (const float*)d_in[0];
    const int*   ei  = (const int*)  d_in[1];
    const float* ew  = (const float*)d_in[2];
    const float* W1r = (const float*)d_in[3];
    const float* b1  = (const float*)d_in[4];
    const float* W1o = (const float*)d_in[5];
    const float* W2r = (const float*)d_in[6];
    const float* b2  = (const float*)d_in[7];
    const float* W2o = (const float*)d_in[8];
    const float* W3r = (const float*)d_in[9];
    const float* b3  = (const float*)d_in[10];
    const float* W3o = (const float*)d_in[11];
    const float* Wl  = (const float*)d_in[12];
    const float* bl  = (const float*)d_in[13];
    float* out = (float*)d_out;

    cudaFuncSetAttribute(k_gemm_dual, cudaFuncAttributeMaxDynamicSharedMemorySize,
                         GEMM_SMEM);

    const int HALF = NN / 2;
    // launches 0..4 (keeps ncu -s 5 -c 1 capture on gemm layer 1)
    k_zero_cnt<<<(HALF + 255) / 256, 256>>>(0);
    k_zero_cnt<<<(NN - HALF + 255) / 256, 256>>>(HALF);
    k_bucket<<<(EE + 255) / 256, 256>>>(ei, ei + EE, ew);
    k_prep_w<<<6, 256>>>(W1r, W1o, W2r, W2o, W3r, W3o);
    k_x0h<<<(NN * CC / 4 + 255) / 256, 256>>>((const float4*)x0);

    dim3 ggrid((NN + AM - 1) / AM, 2);   // 1563 x 2

    // layer 1 (launch 5 = ncu capture)
    k_gemm_dual<<<ggrid, 256, GEMM_SMEM>>>(0, b1);
    k_agg<<<NN / 8, 256>>>();
    // layer 2
    k_gemm_dual<<<ggrid, 256, GEMM_SMEM>>>(2, b2);
    k_agg<<<NN / 8, 256>>>();
    // layer 3
    k_gemm_dual<<<ggrid, 256, GEMM_SMEM>>>(4, b3);
    k_agg<<<NN / 8, 256>>>();
    // head
    k_head<<<NN / 8, 256>>>(Wl, bl, out);
}